// round 4
// baseline (speedup 1.0000x reference)
#include <cuda_runtime.h>

#define T_STEPS 2048
#define N_IN    512
#define N_OUT   512
#define N_OBS   256

// Scratch (padded so prefetch reads stay in-bounds):
//   g_c[t] = x_t . x_{t+1}   (0 for t >= T-1)
//   g_d[t] = x_t . x_{t+2}   (0 for t >= T-2)
__device__ __align__(16) float g_c[T_STEPS + 16];
__device__ __align__(16) float g_d[T_STEPS + 16];

typedef unsigned long long u64;

__device__ __forceinline__ float warp_bfly(float v) {
#pragma unroll
    for (int o = 16; o > 0; o >>= 1)
        v += __shfl_xor_sync(0xffffffffu, v, o);
    return v;
}

// Packed f32x2 FMA: d = a*b + c (per 32-bit half). Blackwell FFMA2.
__device__ __forceinline__ u64 fma2(u64 a, u64 b, u64 c) {
    u64 d;
    asm("fma.rn.f32x2 %0, %1, %2, %3;" : "=l"(d) : "l"(a), "l"(b), "l"(c));
    return d;
}

__device__ __forceinline__ u64 bcast2(float x) {
    u64 d;
    asm("mov.b64 %0, {%1, %1};" : "=l"(d) : "f"(x));
    return d;
}

__device__ __forceinline__ float sum2(u64 v) {
    unsigned int lo, hi;
    asm("mov.b64 {%0, %1}, %2;" : "=r"(lo), "=r"(hi) : "l"(v));
    return __uint_as_float(lo) + __uint_as_float(hi);
}

// ---------------- pre-kernel: c[t], d[t] in parallel (one warp per t) ----
__global__ void precompute_cd_kernel(const float* __restrict__ X) {
    const int t    = blockIdx.x * (blockDim.x >> 5) + (threadIdx.x >> 5);
    const int lane = threadIdx.x & 31;
    if (t >= T_STEPS + 8) return;

    const int t0 = (t     < T_STEPS) ? t     : T_STEPS - 1;
    const int t1 = (t + 1 < T_STEPS) ? t + 1 : T_STEPS - 1;
    const int t2 = (t + 2 < T_STEPS) ? t + 2 : T_STEPS - 1;

    float pc = 0.0f, pd = 0.0f;
#pragma unroll
    for (int g = 0; g < 4; g++) {
        const float4 a  = *reinterpret_cast<const float4*>(&X[t0 * N_IN + g * 128 + lane * 4]);
        const float4 b1 = *reinterpret_cast<const float4*>(&X[t1 * N_IN + g * 128 + lane * 4]);
        const float4 b2 = *reinterpret_cast<const float4*>(&X[t2 * N_IN + g * 128 + lane * 4]);
        pc = fmaf(a.x, b1.x, pc); pc = fmaf(a.y, b1.y, pc);
        pc = fmaf(a.z, b1.z, pc); pc = fmaf(a.w, b1.w, pc);
        pd = fmaf(a.x, b2.x, pd); pd = fmaf(a.y, b2.y, pd);
        pd = fmaf(a.z, b2.z, pd); pd = fmaf(a.w, b2.w, pd);
    }
    const float c = warp_bfly(pc);
    const float d = warp_bfly(pd);
    if (lane == 0) {
        g_c[t] = (t < T_STEPS - 1) ? c : 0.0f;
        g_d[t] = (t < T_STEPS - 2) ? d : 0.0f;
    }
}

// ---------------- main scan: one warp per output row, 2 warps/SMSP ------
// W = alpha * V. Reduction result deferred TWO iterations:
//   at iter t:  u = alpha_{t-1} * q_{t-2};  v = a_{t-1}*u + b_{t-1}*d_{t-1}
//               s_{t+1} = a_t * v + b_t * c_t
//   q_t = bfly( V_{t+1} . x_{t+3} )  -- consumed at iter t+2
__global__ __launch_bounds__(256, 1)
void circuit_scan_kernel(const float* __restrict__ X,
                         const float* __restrict__ W_init,
                         const float* __restrict__ theta,
                         const int*   __restrict__ obs,
                         float*       __restrict__ out)
{
    const int warp = blockIdx.x * 8 + (threadIdx.x >> 5);
    const int lane = threadIdx.x & 31;
    const int row  = warp;

    const float lr  = 1.0f / (float)N_IN;
    const float th0 = __ldg(&theta[0]) * lr;
    const float th1 = __ldg(&theta[1]) * lr;

    // [start, start+count) = this row's slots in the sorted observed_idx
    int start = 0, count = 0;
#pragma unroll 8
    for (int i = 0; i < N_OBS; i++) {
        const int v = __ldg(&obs[i]);
        start += (v <  row) ? 1 : 0;
        count += (v == row) ? 1 : 0;
    }

    // V = W row (alpha = 1), packed f32x2: V[2g+h] covers cols g*128 + lane*4 + 2h..+1
    u64 V[8];
#pragma unroll
    for (int g = 0; g < 4; g++) {
        const ulonglong2 L = *reinterpret_cast<const ulonglong2*>(&W_init[row * N_IN + g * 128 + lane * 4]);
        V[2 * g] = L.x; V[2 * g + 1] = L.y;
    }

    // x ring: xb[k&3] = x_k (packed), k = 0..3
    u64 xb[4][8];
#pragma unroll
    for (int k = 0; k < 4; k++)
#pragma unroll
        for (int g = 0; g < 4; g++) {
            const ulonglong2 L = *reinterpret_cast<const ulonglong2*>(&X[k * N_IN + g * 128 + lane * 4]);
            xb[k][2 * g] = L.x; xb[k][2 * g + 1] = L.y;
        }

    // Prologue reduces: s0 = V0.x0, q2 = V0.x1, q1 = V0.x2
    float s, q2, q1;
    {
        u64 a0 = 0, a1 = 0, a2 = 0;
#pragma unroll
        for (int p = 0; p < 8; p++) {
            a0 = fma2(V[p], xb[0][p], a0);
            a1 = fma2(V[p], xb[1][p], a1);
            a2 = fma2(V[p], xb[2][p], a2);
        }
        s  = warp_bfly(sum2(a0));
        q2 = warp_bfly(sum2(a1));   // q_{-2} = V_0.x_1  (a_{-1}=1, b_{-1}=0)
        q1 = warp_bfly(sum2(a2));   // q_{-1} = V_0.x_2
    }

    float alpha = 1.0f;                             // alpha_t
    float al_pr = 1.0f, a_pr = 1.0f, b_pr = 0.0f;   // alpha_{t-1}, a_{t-1}, b_{t-1}
    float c_cur = __ldg(&g_c[0]);                   // c_t
    float d_pr  = 0.0f;                             // d_{t-1}

    for (int tb = 0; tb < T_STEPS; tb += 4) {
#pragma unroll
        for (int j = 0; j < 4; j++) {
            const int t = tb + j;

            const float c_nxt = __ldg(&g_c[t + 1]);
            const float d_cur = __ldg(&g_d[t]);

            // v-chain: only iteration-start-ready inputs (overlaps sigmoid)
            const float u = al_pr * q2;
            const float v = fmaf(a_pr, u, b_pr * d_pr);

            // sigmoid
            const float e = __expf(-s);
            const float y = __fdividef(1.0f, 1.0f + e);

            // observed outputs
            for (int k = lane; k < count; k += 32)
                out[t * N_OBS + start + k] = y;

            const float b = th0 * y;
            const float a = fmaf(th1 * y, y, 1.0f);
            s = fmaf(a, v, b * c_cur);               // s_{t+1}

            const float alpha_nx = alpha * a;        // alpha_{t+1}
            const float beta     = __fdividef(b, alpha_nx);
            const u64   beta2    = bcast2(beta);

            al_pr = alpha; a_pr = a; b_pr = b;
            alpha = alpha_nx;
            c_cur = c_nxt; d_pr = d_cur;

            // V update (x_t) fused with partial dot against x_{t+3} — packed f32x2
            u64* xt = xb[j];
            u64* xd = xb[(j + 3) & 3];
            u64 w0 = 0, w1 = 0, w2 = 0, w3 = 0;
#pragma unroll
            for (int g = 0; g < 4; g++) {
                V[2 * g]     = fma2(beta2, xt[2 * g],     V[2 * g]);
                V[2 * g + 1] = fma2(beta2, xt[2 * g + 1], V[2 * g + 1]);
                w0 = fma2(V[2 * g],     xd[2 * g],     w0);
                w1 = fma2(V[2 * g + 1], xd[2 * g + 1], w1);
            }
            // (w2,w3 unused; kept names minimal)
            const float qf = (sum2(w0) + sum2(w1));
            const float q_new = warp_bfly(qf);        // V_{t+1}.x_{t+3}
            q2 = q1;
            q1 = q_new;

            // refill ring slot with x_{t+4} (clamped; tail values unused)
            int tn = t + 4;
            if (tn > T_STEPS - 1) tn = T_STEPS - 1;
#pragma unroll
            for (int g = 0; g < 4; g++) {
                const ulonglong2 L = *reinterpret_cast<const ulonglong2*>(&X[tn * N_IN + g * 128 + lane * 4]);
                xb[j][2 * g] = L.x; xb[j][2 * g + 1] = L.y;
            }
        }
    }
}

extern "C" void kernel_launch(void* const* d_in, const int* in_sizes, int n_in,
                              void* d_out, int out_size)
{
    const float* X      = (const float*)d_in[0];   // [2048, 512]
    const float* W_init = (const float*)d_in[1];   // [512, 512]
    const float* theta  = (const float*)d_in[2];   // [2]
    const int*   obs    = (const int*)d_in[3];     // [256], sorted
    float*       out    = (float*)d_out;           // [2048, 256]

    (void)in_sizes; (void)n_in; (void)out_size;

    precompute_cd_kernel<<<257, 256>>>(X);
    // 512 rows -> 512 warps -> 64 CTAs x 256 threads (8 warps/CTA, 2 warps/SMSP)
    circuit_scan_kernel<<<64, 256>>>(X, W_init, theta, obs, out);
}

// round 5
// speedup vs baseline: 1.8556x; 1.8556x over previous
#include <cuda_runtime.h>

#define T_STEPS 2048
#define N_IN    512
#define N_OUT   512
#define N_OBS   256

// e table: g_e[t*8 + (k-1)] = x_t . x_{t+k} for k=1..5 (0 when t+k >= T). Slots 5..7 = 0.
__device__ __align__(16) float g_e[(T_STEPS + 8) * 8];

typedef unsigned long long u64;

__device__ __forceinline__ float warp_bfly(float v) {
#pragma unroll
    for (int o = 16; o > 0; o >>= 1)
        v += __shfl_xor_sync(0xffffffffu, v, o);
    return v;
}

// Packed f32x2 FMA (Blackwell FFMA2): d = a*b + c per 32-bit half
__device__ __forceinline__ u64 fma2(u64 a, u64 b, u64 c) {
    u64 d;
    asm("fma.rn.f32x2 %0, %1, %2, %3;" : "=l"(d) : "l"(a), "l"(b), "l"(c));
    return d;
}
__device__ __forceinline__ u64 bcast2(float x) {
    u64 d;
    asm("mov.b64 %0, {%1, %1};" : "=l"(d) : "f"(x));
    return d;
}
__device__ __forceinline__ float sum2(u64 v) {
    unsigned int lo, hi;
    asm("mov.b64 {%0, %1}, %2;" : "=r"(lo), "=r"(hi) : "l"(v));
    return __uint_as_float(lo) + __uint_as_float(hi);
}
// load 16 consecutive-per-lane floats (cols lane*4 + g*128) as 8 packed u64
__device__ __forceinline__ void load_row(u64* dst, const float* base_lane) {
#pragma unroll
    for (int g = 0; g < 4; g++) {
        const ulonglong2 L = *reinterpret_cast<const ulonglong2*>(base_lane + g * 128);
        dst[2 * g] = L.x; dst[2 * g + 1] = L.y;
    }
}

// ---------------- pre-kernel: e_k[t] = x_t . x_{t+k}, k=1..5 ----------------
__global__ void precompute_e_kernel(const float* __restrict__ X) {
    const int t    = blockIdx.x * 8 + (threadIdx.x >> 5);
    const int lane = threadIdx.x & 31;
    if (t >= T_STEPS) return;

    float4 xt[4];
#pragma unroll
    for (int g = 0; g < 4; g++)
        xt[g] = *reinterpret_cast<const float4*>(&X[t * N_IN + g * 128 + lane * 4]);

    float acc[5];
#pragma unroll
    for (int k = 1; k <= 5; k++) {
        const bool valid = (t + k) < T_STEPS;
        const int  tk    = valid ? (t + k) : (T_STEPS - 1);
        float p = 0.0f;
#pragma unroll
        for (int g = 0; g < 4; g++) {
            const float4 xk = *reinterpret_cast<const float4*>(&X[tk * N_IN + g * 128 + lane * 4]);
            p = fmaf(xt[g].x, xk.x, p); p = fmaf(xt[g].y, xk.y, p);
            p = fmaf(xt[g].z, xk.z, p); p = fmaf(xt[g].w, xk.w, p);
        }
        p = warp_bfly(p);
        acc[k - 1] = valid ? p : 0.0f;
    }
    if (lane == 0) {
#pragma unroll
        for (int k = 0; k < 5; k++) g_e[t * 8 + k] = acc[k];
        g_e[t * 8 + 5] = 0.0f; g_e[t * 8 + 6] = 0.0f; g_e[t * 8 + 7] = 0.0f;
    }
}

// ---------------- main scan: one warp per row, 1 warp/SMSP ----------------
// s_u = alpha_u*(Q_u + ring[u&7]) + b_{u-1}*e1[u-1]
//   Q_u = V_{u-5} . x_u   (butterfly pipelined: 1 stage/iteration, 5 in flight)
//   ring collects beta_{u-k}*e_k[u-k] for k=2..5
__global__ __launch_bounds__(128, 1)
void circuit_scan_kernel(const float* __restrict__ X,
                         const float* __restrict__ W_init,
                         const float* __restrict__ theta,
                         const int*   __restrict__ obs,
                         float*       __restrict__ out)
{
    const int warp = blockIdx.x * 4 + (threadIdx.x >> 5);
    const int lane = threadIdx.x & 31;
    const int row  = warp;

    const float lr  = 1.0f / (float)N_IN;
    const float th0 = __ldg(&theta[0]) * lr;
    const float th1 = __ldg(&theta[1]) * lr;

    int start = 0, count = 0;
#pragma unroll 8
    for (int i = 0; i < N_OBS; i++) {
        const int v = __ldg(&obs[i]);
        start += (v <  row) ? 1 : 0;
        count += (v == row) ? 1 : 0;
    }

    const float* Xl = X + lane * 4;   // lane-adjusted base

    u64 V[8];
    load_row(V, &W_init[row * N_IN + lane * 4]);

    float ring[8] = {0.f, 0.f, 0.f, 0.f, 0.f, 0.f, 0.f, 0.f};
    float alpha = 1.0f;
    float term1 = 0.0f;
    float pp[8];

    // ---- prologue: u = 0..7, direct dots (slow path, primes everything) ----
#pragma unroll
    for (int u = 0; u < 8; u++) {
        u64 xu[8];
        load_row(xu, Xl + u * N_IN);

        u64 a0 = 0, a1 = 0;
#pragma unroll
        for (int g = 0; g < 4; g++) {
            a0 = fma2(V[2 * g],     xu[2 * g],     a0);
            a1 = fma2(V[2 * g + 1], xu[2 * g + 1], a1);
        }
        const float s = alpha * warp_bfly(sum2(a0) + sum2(a1));
        const float e = __expf(-s);
        const float y = __fdividef(1.0f, 1.0f + e);
        if (lane < count) out[u * N_OBS + start + lane] = y;

        const float b = th0 * y;
        const float a = fmaf(th1 * y, y, 1.0f);
        const float alpha_nx = alpha * a;
        const float beta = __fdividef(b, alpha_nx);
        alpha = alpha_nx;

        if (u == 7) term1 = b * __ldg(&g_e[u * 8 + 0]);
#pragma unroll
        for (int k = 2; k <= 5; k++)
            if (u + k >= 8)
                ring[(u + k) & 7] += beta * __ldg(&g_e[u * 8 + k - 1]);

        // V update, then partial of P_u = V_{u+1} . x_{u+6}
        u64 xg[8];
        load_row(xg, Xl + (u + 6) * N_IN);
        const u64 b2 = bcast2(beta);
        u64 w0 = 0, w1 = 0;
#pragma unroll
        for (int g = 0; g < 4; g++) {
            V[2 * g]     = fma2(b2, xu[2 * g],     V[2 * g]);
            V[2 * g + 1] = fma2(b2, xu[2 * g + 1], V[2 * g + 1]);
            w0 = fma2(V[2 * g],     xg[2 * g],     w0);
            w1 = fma2(V[2 * g + 1], xg[2 * g + 1], w1);
        }
        pp[u] = sum2(w0) + sum2(w1);
    }

    // ---- prime the butterfly pipeline from pp[2..7] ----
    float Q = pp[2];
    Q += __shfl_xor_sync(~0u, Q, 16); Q += __shfl_xor_sync(~0u, Q, 8);
    Q += __shfl_xor_sync(~0u, Q, 4);  Q += __shfl_xor_sync(~0u, Q, 2);
    Q += __shfl_xor_sync(~0u, Q, 1);
    float r5 = pp[3];
    r5 += __shfl_xor_sync(~0u, r5, 16); r5 += __shfl_xor_sync(~0u, r5, 8);
    r5 += __shfl_xor_sync(~0u, r5, 4);  r5 += __shfl_xor_sync(~0u, r5, 2);
    float r4 = pp[4];
    r4 += __shfl_xor_sync(~0u, r4, 16); r4 += __shfl_xor_sync(~0u, r4, 8);
    r4 += __shfl_xor_sync(~0u, r4, 4);
    float r3 = pp[5];
    r3 += __shfl_xor_sync(~0u, r3, 16); r3 += __shfl_xor_sync(~0u, r3, 8);
    float r2 = pp[6];
    r2 += __shfl_xor_sync(~0u, r2, 16);
    float r1 = pp[7];

    // ---- x rings (static power-of-2 indexing under unroll-8) ----
    u64 xa[2][8];                          // x_u : slot u&1, distance-1 prefetch (L1 hit)
    load_row(xa[0], Xl + 8 * N_IN);
    load_row(xa[1], Xl + 9 * N_IN);
    u64 xd[4][8];                          // x_{u+6} : slot u&3, distance-4 prefetch (covers L2)
    load_row(xd[0], Xl + 14 * N_IN);
    load_row(xd[1], Xl + 15 * N_IN);
    load_row(xd[2], Xl + 16 * N_IN);
    load_row(xd[3], Xl + 17 * N_IN);

    // e block prefetch for u = 8
    float4 e4 = *reinterpret_cast<const float4*>(&g_e[8 * 8]);
    float  e5 = g_e[8 * 8 + 4];

    // ---- main loop: u = 8 .. 2047 (2040 = 255 * 8 iterations) ----
    for (int tb = 8; tb < T_STEPS; tb += 8) {
#pragma unroll
        for (int j = 0; j < 8; j++) {
            const int u = tb + j;

            // s_u: all inputs ready at iteration start
            const float s = fmaf(alpha, Q + ring[j], term1);
            ring[j] = 0.0f;

            const float e = __expf(-s);
            const float y = __fdividef(1.0f, 1.0f + e);
            if (lane < count) out[u * N_OBS + start + lane] = y;

            const float b = th0 * y;
            const float a = fmaf(th1 * y, y, 1.0f);
            const float alpha_nx = alpha * a;
            const float beta = __fdividef(b, alpha_nx);
            alpha = alpha_nx;

            term1 = b * e4.x;                        // k=1 term for s_{u+1} (no RCP on chain)
            ring[(j + 2) & 7] += beta * e4.y;
            ring[(j + 3) & 7] += beta * e4.z;
            ring[(j + 4) & 7] += beta * e4.w;
            ring[(j + 5) & 7] += beta * e5;

            // prefetch e block for u+1
            e4 = *reinterpret_cast<const float4*>(&g_e[(u + 1) * 8]);
            e5 = g_e[(u + 1) * 8 + 4];

            // V += beta * x_u, fused with partial of P_u = V_{u+1} . x_{u+6}
            u64* xu = xa[j & 1];
            u64* xg = xd[j & 3];
            const u64 b2 = bcast2(beta);
            u64 w0 = 0, w1 = 0;
#pragma unroll
            for (int g = 0; g < 4; g++) {
                V[2 * g]     = fma2(b2, xu[2 * g],     V[2 * g]);
                V[2 * g + 1] = fma2(b2, xu[2 * g + 1], V[2 * g + 1]);
                w0 = fma2(V[2 * g],     xg[2 * g],     w0);
                w1 = fma2(V[2 * g + 1], xg[2 * g + 1], w1);
            }
            const float p = sum2(w0) + sum2(w1);

            // butterfly pipeline: one stage per in-flight reduction, all
            // operands one full iteration old -> no dependent-SHFL stalls
            const float Qn = r5 + __shfl_xor_sync(~0u, r5, 1);   // completes P_{u-5} -> Q_{u+1}
            const float n5 = r4 + __shfl_xor_sync(~0u, r4, 2);
            const float n4 = r3 + __shfl_xor_sync(~0u, r3, 4);
            const float n3 = r2 + __shfl_xor_sync(~0u, r2, 8);
            const float n2 = r1 + __shfl_xor_sync(~0u, r1, 16);
            Q = Qn; r5 = n5; r4 = n4; r3 = n3; r2 = n2; r1 = p;

            // refill rings: xa slot gets x_{u+2}; xd slot gets x_{u+10} (clamped,
            // tail values feed reductions whose Q is never consumed)
            int ta = u + 2;  if (ta > T_STEPS - 1) ta = T_STEPS - 1;
            load_row(xa[j & 1], Xl + ta * N_IN);
            int td = u + 10; if (td > T_STEPS - 1) td = T_STEPS - 1;
            load_row(xd[j & 3], Xl + td * N_IN);
        }
    }
}

extern "C" void kernel_launch(void* const* d_in, const int* in_sizes, int n_in,
                              void* d_out, int out_size)
{
    const float* X      = (const float*)d_in[0];   // [2048, 512]
    const float* W_init = (const float*)d_in[1];   // [512, 512]
    const float* theta  = (const float*)d_in[2];   // [2]
    const int*   obs    = (const int*)d_in[3];     // [256], sorted
    float*       out    = (float*)d_out;           // [2048, 256]

    (void)in_sizes; (void)n_in; (void)out_size;

    // 2048 warps: 256 CTAs x 256 threads (8 warps each)
    precompute_e_kernel<<<256, 256>>>(X);
    // 512 rows -> 512 warps -> 128 CTAs x 128 threads (1 warp/SMSP)
    circuit_scan_kernel<<<128, 128>>>(X, W_init, theta, obs, out);
}